// round 2
// baseline (speedup 1.0000x reference)
#include <cuda_runtime.h>
#include <cstdint>
#include <cstddef>

#define B_TOTAL 65536
#define NGRAPH  64
#define NNODES  2048
#define NEDGES  16384
#define META    64
#define TXD     8
#define NOISE   128
#define RROWS   32    // rows per block (16 row-pairs)
#define NFEAT   41    // chain(1) + trig(32) + tx(8)
#define SPAD    36    // padded row stride (floats), 144B = 16B-aligned

typedef unsigned long long ull;

// Scratch
__device__ float g_go[NGRAPH * NOISE];      // per-graph output contribution (+emb_b)
__device__ float agg_all[NGRAPH * NNODES];  // per-graph GCN node values (*w+b folded)

// ---------- f32x2 helpers ----------
__device__ __forceinline__ ull pack2(float lo, float hi) {
    ull r; asm("mov.b64 %0, {%1,%2};" : "=l"(r) : "f"(lo), "f"(hi)); return r;
}
__device__ __forceinline__ ull fma2(ull a, ull b, ull c) {
    ull d; asm("fma.rn.f32x2 %0, %1, %2, %3;" : "=l"(d) : "l"(a), "l"(b), "l"(c)); return d;
}
__device__ __forceinline__ void unpack2(ull v, float& lo, float& hi) {
    asm("mov.b64 {%0,%1}, %2;" : "=f"(lo), "=f"(hi) : "l"(v));
}

// ============================================================================
// Kernel 1a: per-graph GCN aggregation -> agg_all; also init g_go row with emb_b
// ============================================================================
__global__ __launch_bounds__(512) void gcn_agg(
    const int* __restrict__ edges, const float* __restrict__ gwp,
    const float* __restrict__ gbp, const float* __restrict__ embb)
{
    __shared__ float deg[NNODES];   // then dinv
    __shared__ float agg[NNODES];

    const int g   = blockIdx.x;
    const int tid = threadIdx.x;
    const int* src = edges + (size_t)g * 2 * NEDGES;
    const int* dst = src + NEDGES;

    for (int n = tid; n < NNODES; n += 512) deg[n] = 1.0f;   // self loop
    __syncthreads();
    for (int e = tid; e < NEDGES; e += 512) atomicAdd(&deg[dst[e]], 1.0f);
    __syncthreads();
    for (int n = tid; n < NNODES; n += 512) {
        float dv = rsqrtf(deg[n]);
        deg[n] = dv;
        agg[n] = dv * dv;     // self-loop term
    }
    __syncthreads();
    for (int e = tid; e < NEDGES; e += 512) {
        int s = src[e], d = dst[e];
        atomicAdd(&agg[d], deg[s] * deg[d]);
    }
    __syncthreads();
    const float w = gwp[0], b = gbp[0];
    for (int n = tid; n < NNODES; n += 512)
        agg_all[(size_t)g * NNODES + n] = fmaf(agg[n], w, b);
    if (tid < NOISE) g_go[g * NOISE + tid] = embb[tid];
}

// ============================================================================
// Kernel 1b: g_go += AGG[64,2048] @ embW[:2048,:128]
// grid = 128 blocks = 16 K-splits x 8 graph-splits; 128 threads (col = tid).
// ============================================================================
__global__ __launch_bounds__(128) void gcn_gemm(const float* __restrict__ embW)
{
    __shared__ float aggs[8][128];
    const int tid = threadIdx.x;
    const int ks  = blockIdx.x & 15;   // K slice of 128 rows
    const int gsp = blockIdx.x >> 4;   // 8 graphs

    #pragma unroll
    for (int j = 0; j < 8; j++)
        aggs[j][tid] = agg_all[(size_t)(gsp * 8 + j) * NNODES + ks * 128 + tid];
    __syncthreads();

    float acc[8] = {0.f, 0.f, 0.f, 0.f, 0.f, 0.f, 0.f, 0.f};
    const float* wb = embW + (size_t)ks * 128 * NOISE + tid;
    #pragma unroll 4
    for (int n = 0; n < 128; n++) {
        float wv = __ldg(wb + (size_t)n * NOISE);
        #pragma unroll
        for (int j = 0; j < 8; j++)
            acc[j] = fmaf(aggs[j][n], wv, acc[j]);
    }
    #pragma unroll
    for (int j = 0; j < 8; j++)
        atomicAdd(&g_go[(gsp * 8 + j) * NOISE + tid], acc[j]);
}

// ============================================================================
// Kernel 2: fused trig-MLP + output GEMM.
// 128 threads: lane jq = tid&31 -> cols 4jq..4jq+3 (one LDG.128 of weights/k);
// warp w = tid>>5 -> row-pairs 4w..4w+3 (rows 8w..8w+7), feature loads are
// same-address broadcast LDS.128 (ulonglong2). f32x2 packs the row pair.
// ============================================================================
__global__ __launch_bounds__(128) void noise_main(
    const int*   __restrict__ gid,   const float* __restrict__ chain,
    const float* __restrict__ td,    const float* __restrict__ tx,
    const float* __restrict__ trigW, const float* __restrict__ trigb,
    const float* __restrict__ embW,  float* __restrict__ out)
{
    __shared__ __align__(16) float td_s[META][SPAD];
    __shared__ __align__(16) float feat_s[NFEAT][SPAD];  // 0=chain,1..32=trig,33..40=tx
    __shared__ int gs[RROWS];

    const int tid = threadIdx.x;
    const int r0  = blockIdx.x * RROWS;

    // ---- stage inputs (transposed) ----
    {
        const float4* tdg = reinterpret_cast<const float4*>(td + (size_t)r0 * META);
        for (int i = tid; i < RROWS * (META / 4); i += 128) {
            float4 v = tdg[i];
            int r = i / (META / 4);
            int m = (i % (META / 4)) * 4;
            td_s[m + 0][r] = v.x; td_s[m + 1][r] = v.y;
            td_s[m + 2][r] = v.z; td_s[m + 3][r] = v.w;
        }
        const float4* txg = reinterpret_cast<const float4*>(tx + (size_t)r0 * TXD);
        for (int i = tid; i < RROWS * (TXD / 4); i += 128) {
            float4 v = txg[i];
            int r = i / (TXD / 4);
            int m = (i % (TXD / 4)) * 4;
            feat_s[33 + m + 0][r] = v.x; feat_s[33 + m + 1][r] = v.y;
            feat_s[33 + m + 2][r] = v.z; feat_s[33 + m + 3][r] = v.w;
        }
        if (tid < RROWS) {
            feat_s[0][tid] = chain[r0 + tid];
            gs[tid] = gid[r0 + tid];
        }
    }
    __syncthreads();

    // ---- phase 1: trig = relu(td @ trig_W + trig_b), row-paired ----
    {
        const int k = tid & 31;   // output feature
        const int w = tid >> 5;   // pairs {w, w+4, w+8, w+12}
        float tb = __ldg(&trigb[k]);
        ull acc0 = pack2(tb, tb), acc1 = acc0, acc2 = acc0, acc3 = acc0;
        #pragma unroll 16
        for (int m = 0; m < META; m++) {
            float wv = __ldg(&trigW[m * 32 + k]);
            ull wd = pack2(wv, wv);
            ull t0 = *reinterpret_cast<const ull*>(&td_s[m][2 * (w)]);
            ull t1 = *reinterpret_cast<const ull*>(&td_s[m][2 * (w + 4)]);
            ull t2 = *reinterpret_cast<const ull*>(&td_s[m][2 * (w + 8)]);
            ull t3 = *reinterpret_cast<const ull*>(&td_s[m][2 * (w + 12)]);
            acc0 = fma2(wd, t0, acc0);
            acc1 = fma2(wd, t1, acc1);
            acc2 = fma2(wd, t2, acc2);
            acc3 = fma2(wd, t3, acc3);
        }
        float a, b2;
        unpack2(acc0, a, b2);
        *reinterpret_cast<ull*>(&feat_s[1 + k][2 * (w)])      = pack2(fmaxf(a, 0.f), fmaxf(b2, 0.f));
        unpack2(acc1, a, b2);
        *reinterpret_cast<ull*>(&feat_s[1 + k][2 * (w + 4)])  = pack2(fmaxf(a, 0.f), fmaxf(b2, 0.f));
        unpack2(acc2, a, b2);
        *reinterpret_cast<ull*>(&feat_s[1 + k][2 * (w + 8)])  = pack2(fmaxf(a, 0.f), fmaxf(b2, 0.f));
        unpack2(acc3, a, b2);
        *reinterpret_cast<ull*>(&feat_s[1 + k][2 * (w + 12)]) = pack2(fmaxf(a, 0.f), fmaxf(b2, 0.f));
    }
    __syncthreads();

    // ---- phase 2: output GEMM over 41 features ----
    {
        const int jq = tid & 31;          // col group: cols 4*jq..4*jq+3
        const int w  = tid >> 5;          // pairs 4w..4w+3

        ull acc[4][4];
        // init from g_go gather
        #pragma unroll
        for (int pi = 0; pi < 4; pi++) {
            int p  = 4 * w + pi;
            int ra = 2 * p, rb = ra + 1;
            const float4 ga4 = __ldg(reinterpret_cast<const float4*>(
                &g_go[gs[ra] * NOISE + 4 * jq]));
            const float4 gb4 = __ldg(reinterpret_cast<const float4*>(
                &g_go[gs[rb] * NOISE + 4 * jq]));
            acc[pi][0] = pack2(ga4.x, gb4.x);
            acc[pi][1] = pack2(ga4.y, gb4.y);
            acc[pi][2] = pack2(ga4.z, gb4.z);
            acc[pi][3] = pack2(ga4.w, gb4.w);
        }

        const float4* wrow = reinterpret_cast<const float4*>(embW + (size_t)2048 * NOISE) + jq;
        #pragma unroll 4
        for (int k = 0; k < NFEAT; k++) {
            float4 wv = __ldg(wrow + (size_t)k * (NOISE / 4));
            ull wd0 = pack2(wv.x, wv.x);
            ull wd1 = pack2(wv.y, wv.y);
            ull wd2 = pack2(wv.z, wv.z);
            ull wd3 = pack2(wv.w, wv.w);
            ulonglong2 t01 = *reinterpret_cast<const ulonglong2*>(&feat_s[k][8 * w]);
            ulonglong2 t23 = *reinterpret_cast<const ulonglong2*>(&feat_s[k][8 * w + 4]);
            acc[0][0] = fma2(wd0, t01.x, acc[0][0]);
            acc[0][1] = fma2(wd1, t01.x, acc[0][1]);
            acc[0][2] = fma2(wd2, t01.x, acc[0][2]);
            acc[0][3] = fma2(wd3, t01.x, acc[0][3]);
            acc[1][0] = fma2(wd0, t01.y, acc[1][0]);
            acc[1][1] = fma2(wd1, t01.y, acc[1][1]);
            acc[1][2] = fma2(wd2, t01.y, acc[1][2]);
            acc[1][3] = fma2(wd3, t01.y, acc[1][3]);
            acc[2][0] = fma2(wd0, t23.x, acc[2][0]);
            acc[2][1] = fma2(wd1, t23.x, acc[2][1]);
            acc[2][2] = fma2(wd2, t23.x, acc[2][2]);
            acc[2][3] = fma2(wd3, t23.x, acc[2][3]);
            acc[3][0] = fma2(wd0, t23.y, acc[3][0]);
            acc[3][1] = fma2(wd1, t23.y, acc[3][1]);
            acc[3][2] = fma2(wd2, t23.y, acc[3][2]);
            acc[3][3] = fma2(wd3, t23.y, acc[3][3]);
        }

        // epilogue: unpack row pairs, STG.128 per row
        #pragma unroll
        for (int pi = 0; pi < 4; pi++) {
            int p  = 4 * w + pi;
            size_t ra = (size_t)(r0 + 2 * p);
            float4 lo, hi;
            unpack2(acc[pi][0], lo.x, hi.x);
            unpack2(acc[pi][1], lo.y, hi.y);
            unpack2(acc[pi][2], lo.z, hi.z);
            unpack2(acc[pi][3], lo.w, hi.w);
            *reinterpret_cast<float4*>(out + ra * NOISE + 4 * jq)       = lo;
            *reinterpret_cast<float4*>(out + (ra + 1) * NOISE + 4 * jq) = hi;
        }
    }
}

// ============================================================================
extern "C" void kernel_launch(void* const* d_in, const int* in_sizes, int n_in,
                              void* d_out, int out_size) {
    (void)in_sizes; (void)n_in; (void)out_size;
    const int*   gid   = (const int*)  d_in[0];
    const float* chain = (const float*)d_in[1];
    const float* td    = (const float*)d_in[2];
    const float* tx    = (const float*)d_in[3];
    const int*   edges = (const int*)  d_in[4];
    const float* gw    = (const float*)d_in[5];
    const float* gb    = (const float*)d_in[6];
    const float* trigW = (const float*)d_in[7];
    const float* trigb = (const float*)d_in[8];
    const float* embW  = (const float*)d_in[9];
    const float* embb  = (const float*)d_in[10];
    float* out = (float*)d_out;

    gcn_agg<<<NGRAPH, 512>>>(edges, gw, gb, embb);
    gcn_gemm<<<128, 128>>>(embW);
    noise_main<<<B_TOTAL / RROWS, 128>>>(gid, chain, td, tx, trigW, trigb, embW, out);
}